// round 6
// baseline (speedup 1.0000x reference)
#include <cuda_runtime.h>
#include <cuda_bf16.h>
#include <math.h>
#include <stdint.h>

#define NSTMT 100000
#define NFUNC 50000
#define NTOT  150000
#define CDIM  128
#define NH    8
#define HD    16
#define NE    200000
#define NTOK  16
#define CC    (CDIM*CDIM)

// ---------------- scratch (static device globals; no allocation) ----------------
__device__ __align__(16) float g_q[(size_t)NTOT*CDIM];                // q (fp32, edge input)
__device__ __align__(16) float g_kr[(size_t)(2*NSTMT+NFUNC)*CDIM];    // k_r per relation
__device__ __align__(16) float g_vr[(size_t)(2*NSTMT+NFUNC)*CDIM];    // v_r per relation
__device__ __align__(16) float g_agg[(size_t)NTOT*CDIM];              // agg0(stmt)+aggF(func)
__device__ __align__(16) float g_agg2[(size_t)NSTMT*CDIM];            // agg2 (stmt, rel 2)
__device__ __align__(16) float g_s[(size_t)3*NSTMT*NH];               // softmax denominators
__device__ __align__(16) float g_cw[(size_t)2*3*CC];                  // composed weights f32
__device__ __align__(16) float g_cb[(size_t)2*3*CDIM];                // composed biases
__device__ __align__(16) __nv_bfloat16 g_wthi[(size_t)12*CC];         // W^T hi bf16 [slot][n][k]
__device__ __align__(16) __nv_bfloat16 g_wtlo[(size_t)12*CC];         // W^T lo bf16
__device__ __align__(16) __nv_bfloat16 g_phi[(size_t)NTOT*CDIM];      // pooled / agg-prep hi
__device__ __align__(16) __nv_bfloat16 g_plo[(size_t)NTOT*CDIM];      // pooled / agg-prep lo
__device__ __align__(16) __nv_bfloat16 g_xhi[(size_t)NTOT*CDIM];      // x hi
__device__ __align__(16) __nv_bfloat16 g_xlo[(size_t)NTOT*CDIM];      // x lo

// slab tables: [table][slab] -> W^T hi/lo, bias, out
__device__ const __nv_bfloat16* g_Whiv[6][5];
__device__ const __nv_bfloat16* g_Wlov[6][5];
__device__ const float*         g_Bv[6][5];
__device__ float*               g_Ov[6][5];

// ---------------- helpers ----------------
__device__ __forceinline__ float gelu_f(float x) {
    float x3 = x*x*x;
    return 0.5f*x*(1.0f + tanhf(0.7978845608028654f*(x + 0.044715f*x3)));
}
__device__ __forceinline__ uint32_t smem_u32(const void* p) {
    uint32_t a;
    asm("{ .reg .u64 t; cvta.to.shared.u64 t, %1; cvt.u32.u64 %0, t; }" : "=r"(a) : "l"(p));
    return a;
}
__device__ __forceinline__ void ldsm4(uint32_t (&r)[4], uint32_t addr) {
    asm volatile("ldmatrix.sync.aligned.m8n8.x4.shared.b16 {%0,%1,%2,%3}, [%4];"
        : "=r"(r[0]), "=r"(r[1]), "=r"(r[2]), "=r"(r[3]) : "r"(addr));
}
__device__ __forceinline__ void mma_bf16(float (&c)[4], const uint32_t (&a)[4],
                                         uint32_t b0, uint32_t b1) {
    asm volatile("mma.sync.aligned.m16n8k16.row.col.f32.bf16.bf16.f32 "
        "{%0,%1,%2,%3}, {%4,%5,%6,%7}, {%8,%9}, {%0,%1,%2,%3};"
        : "+f"(c[0]), "+f"(c[1]), "+f"(c[2]), "+f"(c[3])
        : "r"(a[0]), "r"(a[1]), "r"(a[2]), "r"(a[3]), "r"(b0), "r"(b1));
}
__device__ __forceinline__ void cpa16(uint32_t saddr, const void* g, bool pred) {
    int sz = pred ? 16 : 0;
    asm volatile("cp.async.cg.shared.global [%0], [%1], 16, %2;"
        :: "r"(saddr), "l"(g), "r"(sz) : "memory");
}
// pack two floats into bf16x2 hi word + residual lo word
__device__ __forceinline__ uint32_t pk2(float a, float b, uint32_t& lo) {
    __nv_bfloat16 ha = __float2bfloat16(a), hb = __float2bfloat16(b);
    float fa = __bfloat162float(ha), fb = __bfloat162float(hb);
    __nv_bfloat16 la = __float2bfloat16(a - fa), lb = __float2bfloat16(b - fb);
    lo = (uint32_t)__bfloat16_as_ushort(la) | ((uint32_t)__bfloat16_as_ushort(lb) << 16);
    return (uint32_t)__bfloat16_as_ushort(ha) | ((uint32_t)__bfloat16_as_ushort(hb) << 16);
}

// ---------------- bf16x3 tensor-core GEMM: 128x128 tile, 8 warps, cp.async pipeline ----
// smem per stage: A_hi/A_lo/W_hi/W_lo, each 128 rows x 40 bf16 (80B stride; 32 data + pad)
#define ROWB   80
#define REGSZ  10240
#define KSTAGE 40960
#define OFF_AHI 0
#define OFF_ALO 10240
#define OFF_WHI 20480
#define OFF_WLO 30720

// EPI: 0 = relu + split-write(xhi/xlo), 1 = plain fp32, 2 = skip-blend + split-write
template<int EPI>
__global__ __launch_bounds__(256, 2) void bmma_k(
    const __nv_bfloat16* __restrict__ Ahi, const __nv_bfloat16* __restrict__ Alo,
    int M, int slot,
    __nv_bfloat16* __restrict__ xhi, __nv_bfloat16* __restrict__ xlo,
    const float* __restrict__ xold, const float* __restrict__ skipv)
{
    extern __shared__ char smem[];
    const uint32_t sb = smem_u32(smem);
    const int tid = threadIdx.x;
    const int lane = tid & 31, wid = tid >> 5;
    const int row0 = blockIdx.x * 128;
    const int by = blockIdx.y;
    const __nv_bfloat16* __restrict__ Whi = g_Whiv[slot][by];
    const __nv_bfloat16* __restrict__ Wlo = g_Wlov[slot][by];
    const float* __restrict__ bias = g_Bv[slot][by];
    float* __restrict__ out = g_Ov[slot][by];

    const int m0 = (wid >> 1) * 32;
    const int n0 = (wid & 1) * 64;

    float c[2][8][4];
#pragma unroll
    for (int i = 0; i < 2; i++)
#pragma unroll
        for (int j = 0; j < 8; j++)
#pragma unroll
            for (int k = 0; k < 4; k++) c[i][j][k] = 0.f;

    // ldmatrix lane addressing
    const int i8 = lane & 7, sel = lane >> 3;
    const int aRow = (sel & 1) * 8 + i8;   // + m0 + mf*16 ; chunk += sel>>1
    const int aCs  = sel >> 1;
    const int bRow = (sel >> 1) * 8 + i8;  // + nb ; chunk += sel&1
    const int bCs  = sel & 1;

    // cp.async chunk loader: 2 quads per thread per array (512 quads of 16B each)
    auto chunk_load = [&](int ch, int stage) {
#pragma unroll
        for (int qi = 0; qi < 2; qi++) {
            int q = tid + qi * 256;
            int r = q >> 2, qq = q & 3;
            uint32_t so = sb + (uint32_t)stage * KSTAGE + (uint32_t)(r * ROWB + qq * 16);
            bool pred = (row0 + r) < M;
            const __nv_bfloat16* gh = Ahi + (size_t)(row0 + r) * CDIM + ch * 32 + qq * 8;
            const __nv_bfloat16* gl = Alo + (size_t)(row0 + r) * CDIM + ch * 32 + qq * 8;
            cpa16(so + OFF_AHI, pred ? (const void*)gh : (const void*)Ahi, pred);
            cpa16(so + OFF_ALO, pred ? (const void*)gl : (const void*)Alo, pred);
            cpa16(so + OFF_WHI, Whi + (size_t)r * CDIM + ch * 32 + qq * 8, true);
            cpa16(so + OFF_WLO, Wlo + (size_t)r * CDIM + ch * 32 + qq * 8, true);
        }
        asm volatile("cp.async.commit_group;" ::: "memory");
    };

    auto compute_chunk = [&](int stage) {
        uint32_t stb = sb + (uint32_t)stage * KSTAGE;
#pragma unroll
        for (int ks = 0; ks < 2; ks++) {
            int c2 = ks * 2;
            uint32_t ah[2][4], al[2][4];
#pragma unroll
            for (int mf = 0; mf < 2; mf++) {
                uint32_t ra = stb + (uint32_t)((m0 + mf*16 + aRow) * ROWB + (c2 + aCs) * 16);
                ldsm4(ah[mf], ra + OFF_AHI);
                ldsm4(al[mf], ra + OFF_ALO);
            }
#pragma unroll
            for (int half = 0; half < 2; half++) {
                uint32_t bh[2][4], bl[2][4];
#pragma unroll
                for (int j = 0; j < 2; j++) {
                    uint32_t rb = stb + (uint32_t)((n0 + half*32 + j*16 + bRow) * ROWB
                                                   + (c2 + bCs) * 16);
                    ldsm4(bh[j], rb + OFF_WHI);
                    ldsm4(bl[j], rb + OFF_WLO);
                }
#pragma unroll
                for (int j = 0; j < 2; j++)
#pragma unroll
                    for (int nn = 0; nn < 2; nn++) {
                        int nf = half*4 + j*2 + nn;
                        uint32_t b0h = bh[j][nn*2], b1h = bh[j][nn*2+1];
                        uint32_t b0l = bl[j][nn*2], b1l = bl[j][nn*2+1];
#pragma unroll
                        for (int mf = 0; mf < 2; mf++) {
                            mma_bf16(c[mf][nf], ah[mf], b0h, b1h);
                            mma_bf16(c[mf][nf], ah[mf], b0l, b1l);
                            mma_bf16(c[mf][nf], al[mf], b0h, b1h);
                        }
                    }
            }
        }
    };

    chunk_load(0, 0);
    asm volatile("cp.async.wait_group 0;" ::: "memory");
    __syncthreads();
#pragma unroll
    for (int ch = 0; ch < 4; ch++) {
        if (ch < 3) chunk_load(ch + 1, (ch + 1) & 1);
        compute_chunk(ch & 1);
        if (ch < 3) {
            asm volatile("cp.async.wait_group 0;" ::: "memory");
            __syncthreads();
        }
    }

    // ---- epilogue ----
    const int gp = lane >> 2, tig = lane & 3;
    float gg = 0.f, og = 0.f;
    if (EPI == 2) { gg = 1.0f / (1.0f + expf(-*skipv)); og = 1.0f - gg; }
#pragma unroll
    for (int mf = 0; mf < 2; mf++) {
        int ra = row0 + m0 + mf*16 + gp;
#pragma unroll
        for (int half = 0; half < 2; half++) {
            int rr = ra + half*8;
            if (rr >= M) continue;
#pragma unroll
            for (int nf = 0; nf < 8; nf++) {
                int col = n0 + nf*8 + 2*tig;
                float2 bb = *reinterpret_cast<const float2*>(&bias[col]);
                float v0 = c[mf][nf][half*2+0] + bb.x;
                float v1 = c[mf][nf][half*2+1] + bb.y;
                if (EPI == 0) { v0 = fmaxf(v0, 0.f); v1 = fmaxf(v1, 0.f); }
                if (EPI == 2) {
                    float2 xo = *reinterpret_cast<const float2*>(&xold[(size_t)rr*CDIM + col]);
                    v0 = gg*v0 + og*xo.x; v1 = gg*v1 + og*xo.y;
                }
                *reinterpret_cast<float2*>(&out[(size_t)rr*CDIM + col]) = make_float2(v0, v1);
                if (EPI != 1) {
                    uint32_t lo, hi = pk2(v0, v1, lo);
                    size_t o = ((size_t)rr*CDIM + col);
                    *reinterpret_cast<uint32_t*>(reinterpret_cast<char*>(xhi) + o*2) = hi;
                    *reinterpret_cast<uint32_t*>(reinterpret_cast<char*>(xlo) + o*2) = lo;
                }
            }
        }
    }
}

// ---------------- weight prep: transpose + bf16 split ----------------
struct PrepSrc { const float* s[10]; int n; int slot0; };

__global__ void prep_w_k(PrepSrc ps) {
    int idx = blockIdx.x * blockDim.x + threadIdx.x;
    int m = idx >> 11;                 // 2048 threads per matrix
    if (m >= ps.n) return;
    int rem = idx & 2047;
    int n = rem >> 4;
    int k0 = (rem & 15) * 8;
    const float* W = ps.s[m];
    uint32_t hi[4], lo[4];
#pragma unroll
    for (int i = 0; i < 4; i++) {
        float a = W[(size_t)(k0 + 2*i    ) * CDIM + n];
        float b = W[(size_t)(k0 + 2*i + 1) * CDIM + n];
        hi[i] = pk2(a, b, lo[i]);
    }
    size_t o = (size_t)(ps.slot0 + m) * CC + (size_t)n * CDIM + k0;
    *reinterpret_cast<uint4*>(g_wthi + o) = make_uint4(hi[0], hi[1], hi[2], hi[3]);
    *reinterpret_cast<uint4*>(g_wtlo + o) = make_uint4(lo[0], lo[1], lo[2], lo[3]);
}

// ---------------- slab table setup (device-side, 1 thread) ----------------
__global__ void set_enc_k(const float* lin_b, float* x) {
    const size_t XF = (size_t)NSTMT*CDIM;
    g_Whiv[0][0] = g_wthi;          g_Wlov[0][0] = g_wtlo;
    g_Bv[0][0] = lin_b;             g_Ov[0][0] = x;
    g_Whiv[1][0] = g_wthi + CC;     g_Wlov[1][0] = g_wtlo + CC;
    g_Bv[1][0] = lin_b + CDIM;      g_Ov[1][0] = x + XF;
}

__global__ void set_layer_k(const float* qb, const float* ab, float* x, int l) {
    const size_t XF = (size_t)NSTMT*CDIM;
    // slots in g_wthi: 2=q_st 3=q_fn 4=k0 5=k1 6=k2 7=v0 8=v1 9=v2 10=a_st 11=a_fn
    // table 2: stmt projections [q_st, k0, v0, k1, v1]
    int s2[5] = {2, 4, 7, 5, 8};
    const float* b2[5] = {qb + (size_t)(l*2+0)*CDIM, g_cb + 0*CDIM, g_cb + 3*CDIM,
                          g_cb + 1*CDIM, g_cb + 4*CDIM};
    float* o2[5] = {g_q, g_kr, g_vr, g_kr + XF, g_vr + XF};
    for (int i = 0; i < 5; i++) {
        g_Whiv[2][i] = g_wthi + (size_t)s2[i]*CC; g_Wlov[2][i] = g_wtlo + (size_t)s2[i]*CC;
        g_Bv[2][i] = b2[i]; g_Ov[2][i] = o2[i];
    }
    // table 3: func projections [q_fn, k2, v2]
    int s3[3] = {3, 6, 9};
    const float* b3[3] = {qb + (size_t)(l*2+1)*CDIM, g_cb + 2*CDIM, g_cb + 5*CDIM};
    float* o3[3] = {g_q + XF, g_kr + 2*XF, g_vr + 2*XF};
    for (int i = 0; i < 3; i++) {
        g_Whiv[3][i] = g_wthi + (size_t)s3[i]*CC; g_Wlov[3][i] = g_wtlo + (size_t)s3[i]*CC;
        g_Bv[3][i] = b3[i]; g_Ov[3][i] = o3[i];
    }
    // tables 4/5: epilogue stmt/func
    g_Whiv[4][0] = g_wthi + (size_t)10*CC; g_Wlov[4][0] = g_wtlo + (size_t)10*CC;
    g_Bv[4][0] = ab + (size_t)(l*2+0)*CDIM; g_Ov[4][0] = x;
    g_Whiv[5][0] = g_wthi + (size_t)11*CC; g_Wlov[5][0] = g_wtlo + (size_t)11*CC;
    g_Bv[5][0] = ab + (size_t)(l*2+1)*CDIM; g_Ov[5][0] = x + XF;
}

// ---------------- small kernels ----------------
__global__ void fill_k(float* p, float val, int n) {
    int i = blockIdx.x*blockDim.x + threadIdx.x;
    if (i < n) p[i] = val;
}

// embedding gather + mean + relu, split-write bf16 hi/lo
__global__ void pool_k(const int* __restrict__ tok, const float* __restrict__ emb,
                       __nv_bfloat16* __restrict__ phi, __nv_bfloat16* __restrict__ plo, int N) {
    int node = blockIdx.x*2 + (threadIdx.x >> 7);
    int c = threadIdx.x & 127;
    if (node >= N) return;
    const int* tp = tok + (size_t)node*NTOK;
    float s = 0.f;
#pragma unroll
    for (int t = 0; t < NTOK; t++) s += emb[(size_t)tp[t]*CDIM + c];
    s *= (1.0f/NTOK);
    s = s > 0.f ? s : 0.f;
    __nv_bfloat16 h = __float2bfloat16(s);
    __nv_bfloat16 l = __float2bfloat16(s - __bfloat162float(h));
    phi[(size_t)node*CDIM + c] = h;
    plo[(size_t)node*CDIM + c] = l;
}

// agg prep: v = gelu(agg*rs [+ agg2*rs2]); split-write bf16
__global__ void aggprep_k(const float* __restrict__ agg, const float* __restrict__ agg2,
                          const float* __restrict__ S, const float* __restrict__ S2,
                          __nv_bfloat16* __restrict__ phi, __nv_bfloat16* __restrict__ plo,
                          int nelem) {
    int i = blockIdx.x*blockDim.x + threadIdx.x;
    if (i >= nelem) return;
    int row = i >> 7, h = (i & 127) >> 4;
    float v = agg[i] / (S[(size_t)row*NH + h] + 1e-16f);
    if (agg2) v += agg2[i] / (S2[(size_t)row*NH + h] + 1e-16f);
    v = gelu_f(v);
    __nv_bfloat16 hh = __float2bfloat16(v);
    __nv_bfloat16 ll = __float2bfloat16(v - __bfloat162float(hh));
    phi[i] = hh; plo[i] = ll;
}

// compose: cw[kv][r] = W[l,st] @ blockdiag(rel[l,r]); p_rel*scale folded into k-side.
__global__ void compose_k(const float* __restrict__ kw, const float* __restrict__ kb,
                          const float* __restrict__ vw, const float* __restrict__ vb,
                          const float* __restrict__ a_rel, const float* __restrict__ m_rel,
                          const float* __restrict__ p_rel, int l) {
    int idx = blockIdx.x*blockDim.x + threadIdx.x;
    const int total = 2*3*129*128;
    if (idx >= total) return;
    int j = idx & 127; idx >>= 7;
    int i = idx % 129; idx /= 129;
    int r  = idx % 3;
    int kv = idx / 3;
    int st = (r == 2) ? 1 : 0;
    int h = j >> 4, e = j & 15;
    const float* rel = (kv ? m_rel : a_rel) + (size_t)((l*3+r)*NH + h)*HD*HD + e;
    float sc = (kv == 0) ? (p_rel[(l*3+r)*NH + h] * 0.25f) : 1.0f;
    float sum = 0.f;
    if (i < 128) {
        const float* w = (kv ? vw : kw) + (size_t)(l*2+st)*CC + (size_t)i*CDIM + h*HD;
#pragma unroll
        for (int d = 0; d < HD; d++) sum += w[d]*rel[d*HD];
        g_cw[((size_t)(kv*3+r)*CDIM + i)*CDIM + j] = sum*sc;
    } else {
        const float* b = (kv ? vb : kb) + (size_t)(l*2+st)*CDIM + h*HD;
#pragma unroll
        for (int d = 0; d < HD; d++) sum += b[d]*rel[d*HD];
        g_cb[(size_t)(kv*3+r)*CDIM + j] = sum*sc;
    }
}

// ---------------- fused edge kernel (all 3 relations via blockIdx.y) ----------------
struct EdgeArgs {
    const int*   src[3];
    const int*   dst[3];
    const float* q[3];
    const float* kr[3];
    const float* vr[3];
    float*       sb[3];
    float*       agg[3];
};

__global__ void edge_k(EdgeArgs ea, int ne) {
    int e = (blockIdx.x*blockDim.x + threadIdx.x) >> 5;
    int lane = threadIdx.x & 31;
    if (e >= ne) return;
    int r = blockIdx.y;
    int s = ea.src[r][e], d = ea.dst[r][e];
    float4 qv = *reinterpret_cast<const float4*>(ea.q[r]  + (size_t)d*CDIM + lane*4);
    float4 kv = *reinterpret_cast<const float4*>(ea.kr[r] + (size_t)s*CDIM + lane*4);
    float p = qv.x*kv.x + qv.y*kv.y + qv.z*kv.z + qv.w*kv.w;
    p += __shfl_xor_sync(0xffffffffu, p, 1);
    p += __shfl_xor_sync(0xffffffffu, p, 2);
    float ev = __expf(p);
    int h = lane >> 2;
    if ((lane & 3) == 0) atomicAdd(ea.sb[r] + (size_t)d*NH + h, ev);
    float4 v = *reinterpret_cast<const float4*>(ea.vr[r] + (size_t)s*CDIM + lane*4);
    v.x *= ev; v.y *= ev; v.z *= ev; v.w *= ev;
    atomicAdd(reinterpret_cast<float4*>(ea.agg[r] + (size_t)d*CDIM + lane*4), v);
}

// ---------------- host launcher ----------------
static inline int GB(int m) { return (m + 127) / 128; }

extern "C" void kernel_launch(void* const* d_in, const int* in_sizes, int n_in,
                              void* d_out, int out_size) {
    const int* tok_stmt = (const int*)d_in[0];
    const int* tok_func = (const int*)d_in[1];
    const int* esrc[3] = {(const int*)d_in[2], (const int*)d_in[4], (const int*)d_in[6]};
    const int* edst[3] = {(const int*)d_in[3], (const int*)d_in[5], (const int*)d_in[7]};
    const float* emb   = (const float*)d_in[8];
    const float* lin_w = (const float*)d_in[9];
    const float* lin_b = (const float*)d_in[10];
    const float* kw = (const float*)d_in[11];
    const float* kb = (const float*)d_in[12];
    const float* qw = (const float*)d_in[13];
    const float* qb = (const float*)d_in[14];
    const float* vw = (const float*)d_in[15];
    const float* vb = (const float*)d_in[16];
    const float* aw = (const float*)d_in[17];
    const float* ab = (const float*)d_in[18];
    const float* skip  = (const float*)d_in[19];
    const float* a_rel = (const float*)d_in[20];
    const float* m_rel = (const float*)d_in[21];
    const float* p_rel = (const float*)d_in[22];
    float* x = (float*)d_out;

    float *q, *kr, *vr, *agg, *agg2, *sbuf, *cw;
    __nv_bfloat16 *phi, *plo, *xhi, *xlo;
    cudaGetSymbolAddress((void**)&q,    g_q);
    cudaGetSymbolAddress((void**)&kr,   g_kr);
    cudaGetSymbolAddress((void**)&vr,   g_vr);
    cudaGetSymbolAddress((void**)&agg,  g_agg);
    cudaGetSymbolAddress((void**)&agg2, g_agg2);
    cudaGetSymbolAddress((void**)&sbuf, g_s);
    cudaGetSymbolAddress((void**)&cw,   g_cw);
    cudaGetSymbolAddress((void**)&phi,  g_phi);
    cudaGetSymbolAddress((void**)&plo,  g_plo);
    cudaGetSymbolAddress((void**)&xhi,  g_xhi);
    cudaGetSymbolAddress((void**)&xlo,  g_xlo);

    cudaFuncSetAttribute(bmma_k<0>, cudaFuncAttributeMaxDynamicSharedMemorySize, 2*KSTAGE);
    cudaFuncSetAttribute(bmma_k<1>, cudaFuncAttributeMaxDynamicSharedMemorySize, 2*KSTAGE);
    cudaFuncSetAttribute(bmma_k<2>, cudaFuncAttributeMaxDynamicSharedMemorySize, 2*KSTAGE);

    const size_t XF = (size_t)NSTMT*CDIM;

    // ---- encoder ----
    pool_k<<<(NSTMT+1)/2, 256>>>(tok_stmt, emb, phi, plo, NSTMT);
    pool_k<<<(NFUNC+1)/2, 256>>>(tok_func, emb, phi + XF, plo + XF, NFUNC);
    {
        PrepSrc ps{};
        ps.s[0] = lin_w; ps.s[1] = lin_w + CC; ps.n = 2; ps.slot0 = 0;
        prep_w_k<<<(2*2048 + 255)/256, 256>>>(ps);
    }
    set_enc_k<<<1,1>>>(lin_b, x);
    bmma_k<0><<<dim3(GB(NSTMT),1), 256, 2*KSTAGE>>>(phi, plo, NSTMT, 0, xhi, xlo, nullptr, nullptr);
    bmma_k<0><<<dim3(GB(NFUNC),1), 256, 2*KSTAGE>>>(phi + XF, plo + XF, NFUNC, 1,
                                                     xhi + XF, xlo + XF, nullptr, nullptr);

    const size_t roff[3] = {0, XF, 2*XF};

    for (int l = 0; l < 2; l++) {
        compose_k<<<(2*3*129*128 + 255)/256, 256>>>(kw, kb, vw, vb, a_rel, m_rel, p_rel, l);
        {
            PrepSrc ps{};
            ps.s[0] = qw + (size_t)(l*2+0)*CC;   // slot 2
            ps.s[1] = qw + (size_t)(l*2+1)*CC;   // slot 3
            for (int r = 0; r < 3; r++) {
                ps.s[2+r] = cw + (size_t)(0*3+r)*CC;   // slots 4-6 (k)
                ps.s[5+r] = cw + (size_t)(1*3+r)*CC;   // slots 7-9 (v)
            }
            ps.s[8] = aw + (size_t)(l*2+0)*CC;   // slot 10
            ps.s[9] = aw + (size_t)(l*2+1)*CC;   // slot 11
            ps.n = 10; ps.slot0 = 2;
            prep_w_k<<<(10*2048 + 255)/256, 256>>>(ps);
        }
        set_layer_k<<<1,1>>>(qb, ab, x, l);

        // projections from x (split)
        bmma_k<1><<<dim3(GB(NSTMT),5), 256, 2*KSTAGE>>>(xhi, xlo, NSTMT, 2,
                                                        nullptr, nullptr, nullptr, nullptr);
        bmma_k<1><<<dim3(GB(NFUNC),3), 256, 2*KSTAGE>>>(xhi + XF, xlo + XF, NFUNC, 3,
                                                        nullptr, nullptr, nullptr, nullptr);

        fill_k<<<((int)(NTOT*(size_t)CDIM) + 255)/256, 256>>>(agg, 0.f, NTOT*CDIM);
        fill_k<<<((int)(NSTMT*(size_t)CDIM) + 255)/256, 256>>>(agg2, 0.f, NSTMT*CDIM);
        fill_k<<<(3*NSTMT*NH + 255)/256, 256>>>(sbuf, 0.f, 3*NSTMT*NH);

        EdgeArgs ea;
        for (int r = 0; r < 3; r++) {
            ea.src[r] = esrc[r]; ea.dst[r] = edst[r];
            ea.q[r]  = q + ((r == 1) ? XF : 0);
            ea.kr[r] = kr + roff[r];
            ea.vr[r] = vr + roff[r];
            ea.sb[r] = sbuf + (size_t)r*NSTMT*NH;
        }
        ea.agg[0] = agg;
        ea.agg[1] = agg + XF;
        ea.agg[2] = agg2;
        edge_k<<<dim3((NE*32 + 255)/256, 3), 256>>>(ea, NE);

        // agg -> gelu(normalized) split
        aggprep_k<<<((int)(NSTMT*(size_t)CDIM) + 255)/256, 256>>>(
            agg, agg2, sbuf + 0*(size_t)NSTMT*NH, sbuf + 2*(size_t)NSTMT*NH,
            phi, plo, NSTMT*CDIM);
        aggprep_k<<<((int)(NFUNC*(size_t)CDIM) + 255)/256, 256>>>(
            agg + XF, nullptr, sbuf + 1*(size_t)NSTMT*NH, nullptr,
            phi + XF, plo + XF, NFUNC*CDIM);

        // epilogue: x = g*(A @ aw + ab) + (1-g)*x ; also refresh xhi/xlo
        bmma_k<2><<<dim3(GB(NSTMT),1), 256, 2*KSTAGE>>>(phi, plo, NSTMT, 4,
                                                        xhi, xlo, x, skip + l*2 + 0);
        bmma_k<2><<<dim3(GB(NFUNC),1), 256, 2*KSTAGE>>>(phi + XF, plo + XF, NFUNC, 5,
                                                        xhi + XF, xlo + XF, x + XF, skip + l*2 + 1);
    }
}